// round 14
// baseline (speedup 1.0000x reference)
#include <cuda_runtime.h>
#include <cuda_bf16.h>
#include <cstdint>

// ---------------------------------------------------------------------------
// InteractionModule (PhysNet message passing + residual stack)
// All GEMMs on HMMA mma.sync m16n8k16 bf16, hi/lo split 3-term emulation.
// Weights pre-converted per replay into mma B-fragment images (prep_w, which
// also scans idx dtype and zeroes the dst histogram). Edges are permuted into
// dst-sorted order each replay (hist -> scan -> scatter); the edge kernel
// merges same-dst runs in registers, collapsing red.v4 traffic ~5x.
// 7 launches: prep_w, hist, scan, scatter, tc_dual, edge_kernel, res_chain.
// ---------------------------------------------------------------------------

#define SSP_LOG2 0.69314718055994530942f

__device__ __forceinline__ float sspf(float x) {
    return fmaxf(x, 0.0f) + __logf(1.0f + __expf(-fabsf(x))) - SSP_LOG2;
}

constexpr int FD   = 128;
constexpr int NMAX = 50176;
constexpr int EMAX = 602112;

constexpr int RS      = 144;               // A-tile row stride bytes (9 x 16B)
constexpr int TILE64  = 64 * RS;           // 9216 B per [64 x 64] bf16 tile
constexpr int FRAG_SZ = 32768;             // one K-half B-frag image
constexpr int SM_A64  = 4 * TILE64;        // node kernels: 36864 B

__device__ float    g_tdiff[NMAX * FD];
__device__ float    g_t[NMAX * FD];
__device__ char     g_wimg[20 * FRAG_SZ];  // B-frag images (18 square + Gw)
__device__ int      g_cnt[NMAX];           // dst histogram -> cursor
__device__ int      g_perm[EMAX];          // dst-sorted edge permutation
__device__ unsigned g_or = 0u;             // idempotent across replays

// ---------------------------------------------------------------------------
// warp MMA helpers (generic PTX, sm_80+)
// ---------------------------------------------------------------------------
__device__ __forceinline__ uint32_t smem_u32(const void* p) {
    uint32_t a;
    asm("{ .reg .u64 t; cvta.to.shared.u64 t, %1; cvt.u32.u64 %0, t; }"
        : "=r"(a) : "l"(p));
    return a;
}
__device__ __forceinline__ void ldmx4(uint32_t* r, uint32_t addr) {
    asm volatile("ldmatrix.sync.aligned.m8n8.x4.shared.b16 {%0,%1,%2,%3}, [%4];"
                 : "=r"(r[0]), "=r"(r[1]), "=r"(r[2]), "=r"(r[3]) : "r"(addr));
}
__device__ __forceinline__ void mma16816(float* d, const uint32_t* a,
                                         uint32_t b0, uint32_t b1) {
    asm volatile("mma.sync.aligned.m16n8k16.row.col.f32.bf16.bf16.f32 "
                 "{%0,%1,%2,%3}, {%4,%5,%6,%7}, {%8,%9}, {%0,%1,%2,%3};"
                 : "+f"(d[0]), "+f"(d[1]), "+f"(d[2]), "+f"(d[3])
                 : "r"(a[0]), "r"(a[1]), "r"(a[2]), "r"(a[3]),
                   "r"(b0), "r"(b1));
}

__device__ __forceinline__ void split_pack(float a, float b,
                                           uint32_t& hi, uint32_t& lo) {
    __nv_bfloat16 ah = __float2bfloat16(a);
    __nv_bfloat16 bh = __float2bfloat16(b);
    __nv_bfloat16 al = __float2bfloat16(a - __bfloat162float(ah));
    __nv_bfloat16 bl = __float2bfloat16(b - __bfloat162float(bh));
    hi = ((uint32_t)*(uint16_t*)&bh << 16) | *(uint16_t*)&ah;
    lo = ((uint32_t)*(uint16_t*)&bl << 16) | *(uint16_t*)&al;
}

// fill a [64 x 64] fp32 sub-tile (col offset kh*64, row stride src_ld)
// into hi/lo bf16 A-tiles (row stride RS bytes)
template <bool DO_SSP>
__device__ __forceinline__ void fill_64h(char* dst, int hi_off, int lo_off,
                                         const float* __restrict__ src,
                                         int src_ld, int row0, int nrows,
                                         int kh, int t) {
    const int kg = t & 7;
    const int r0 = t >> 3;
#pragma unroll
    for (int p = 0; p < 2; p++) {
        int row = r0 + p * 32;
        float v[8];
        if (row < nrows) {
            const float* rp = src + (size_t)(row0 + row) * src_ld + kh * 64 + kg * 8;
            float4 va = *(const float4*)(rp);
            float4 vb = *(const float4*)(rp + 4);
            v[0] = va.x; v[1] = va.y; v[2] = va.z; v[3] = va.w;
            v[4] = vb.x; v[5] = vb.y; v[6] = vb.z; v[7] = vb.w;
        } else {
#pragma unroll
            for (int i = 0; i < 8; i++) v[i] = 0.0f;
        }
        uint32_t hi[4], lo[4];
#pragma unroll
        for (int i = 0; i < 4; i++) {
            float a = v[2 * i], b = v[2 * i + 1];
            if (DO_SSP) { a = sspf(a); b = sspf(b); }
            split_pack(a, b, hi[i], lo[i]);
        }
        uint32_t off = (uint32_t)row * RS + kg * 16;
        *(uint4*)(dst + hi_off + off) = make_uint4(hi[0], hi[1], hi[2], hi[3]);
        *(uint4*)(dst + lo_off + off) = make_uint4(lo[0], lo[1], lo[2], lo[3]);
    }
}

// fill edge_attr rows selected by the dst-sorted permutation
__device__ __forceinline__ void fill_ea_perm(char* dst, int hi_off, int lo_off,
                                             const float* __restrict__ src,
                                             const int* __restrict__ perm,
                                             int e0, int E, int t) {
    const int kg = t & 7;
    const int r0 = t >> 3;
#pragma unroll
    for (int p = 0; p < 2; p++) {
        int row = r0 + p * 32;
        int e = e0 + row;
        float v[8];
        if (e < E) {
            int eid = perm[e];
            const float* rp = src + (size_t)eid * 64 + kg * 8;
            float4 va = *(const float4*)(rp);
            float4 vb = *(const float4*)(rp + 4);
            v[0] = va.x; v[1] = va.y; v[2] = va.z; v[3] = va.w;
            v[4] = vb.x; v[5] = vb.y; v[6] = vb.z; v[7] = vb.w;
        } else {
#pragma unroll
            for (int i = 0; i < 8; i++) v[i] = 0.0f;
        }
        uint32_t hi[4], lo[4];
#pragma unroll
        for (int i = 0; i < 4; i++)
            split_pack(v[2 * i], v[2 * i + 1], hi[i], lo[i]);
        uint32_t off = (uint32_t)row * RS + kg * 16;
        *(uint4*)(dst + hi_off + off) = make_uint4(hi[0], hi[1], hi[2], hi[3]);
        *(uint4*)(dst + lo_off + off) = make_uint4(lo[0], lo[1], lo[2], lo[3]);
    }
}

// one K=64 MMA pass; A from smem (ldmatrix), B frags via LDG from frag image.
template <int MI>
__device__ __forceinline__ void mma_passG(float acc[MI][4][4],
                                          const uint32_t aHiA[MI],
                                          const uint32_t aLoA[MI],
                                          const uint4* __restrict__ bimg,
                                          int nw, int lane) {
#pragma unroll
    for (int ks = 0; ks < 4; ks++) {
        uint4 b[4];
#pragma unroll
        for (int nj = 0; nj < 4; nj++)
            b[nj] = bimg[((nw * 4 + ks) * 4 + nj) * 32 + lane];
        const uint32_t koff = ks * 32;
        uint32_t af[MI][4];
#pragma unroll
        for (int mi = 0; mi < MI; mi++) ldmx4(af[mi], aHiA[mi] + koff);
#pragma unroll
        for (int mi = 0; mi < MI; mi++)
#pragma unroll
            for (int nj = 0; nj < 4; nj++) {
                mma16816(acc[mi][nj], af[mi], b[nj].x, b[nj].y);   // Ah*Wh
                mma16816(acc[mi][nj], af[mi], b[nj].z, b[nj].w);   // Ah*Wl
            }
#pragma unroll
        for (int mi = 0; mi < MI; mi++) ldmx4(af[mi], aLoA[mi] + koff);
#pragma unroll
        for (int mi = 0; mi < MI; mi++)
#pragma unroll
            for (int nj = 0; nj < 4; nj++)
                mma16816(acc[mi][nj], af[mi], b[nj].x, b[nj].y);   // Al*Wh
    }
}

#define ZERO_ACC2(acc) do {                                                   \
    _Pragma("unroll") for (int mi = 0; mi < 2; mi++)                          \
    _Pragma("unroll") for (int nj = 0; nj < 4; nj++)                          \
    _Pragma("unroll") for (int q = 0; q < 4; q++) (acc)[mi][nj][q] = 0.0f;    \
} while (0)

struct TileIds {
    int lane, w, m_warp, nw, r_in, c_in;
    uint32_t aOff[2];
};
__device__ __forceinline__ TileIds make_ids(int t) {
    TileIds id;
    id.lane  = t & 31;
    id.w     = t >> 5;
    id.m_warp = (id.w >> 2) * 32;
    id.nw    = id.w & 3;
    id.r_in  = id.lane >> 2;
    id.c_in  = (id.lane & 3) * 2;
    const int a_row = id.m_warp + ((id.lane >> 3) & 1) * 8 + (id.lane & 7);
    const int a_kh  = (id.lane >> 4) * 16;
#pragma unroll
    for (int mi = 0; mi < 2; mi++)
        id.aOff[mi] = (uint32_t)(a_row + 16 * mi) * RS + a_kh;
    return id;
}

// ---------------------------------------------------------------------------
// prep_w: weight B-frag images + idx dtype scan + g_cnt zero, one launch.
// ---------------------------------------------------------------------------
constexpr int SCAN_BLKS = 128;
constexpr int ZERO_BLKS = 64;

__global__ void prep_w(const float* __restrict__ Wsame,
                       const float* __restrict__ Wdiff,
                       const float* __restrict__ rW1,
                       const float* __restrict__ rW2,
                       const float* __restrict__ Wlast,
                       const float* __restrict__ Gw, int R,
                       const unsigned* __restrict__ eiw, int E, int N)
{
    const int bq = blockIdx.x, t = threadIdx.x;
    const int nsq = 3 + 2 * R;
    if (bq > 2 * nsq + SCAN_BLKS) {
        // zero blocks for g_cnt
        const int zb = bq - (2 * nsq + 1 + SCAN_BLKS);
        for (int i = zb * 256 + t; i < N; i += ZERO_BLKS * 256)
            g_cnt[i] = 0;
        return;
    }
    if (bq > 2 * nsq) {
        // idx dtype scan blocks
        const int sb = bq - (2 * nsq + 1);
        unsigned v = 0;
        for (int i = sb * 256 + t; i < E; i += SCAN_BLKS * 256)
            v |= eiw[2 * i + 1];
        v = __reduce_or_sync(0xffffffffu, v);
        if ((t & 31) == 0 && v) atomicOr(&g_or, 1u);
        return;
    }
    const float* W;
    int ld, kh;
    char* img;
    if (bq < 2 * nsq) {
        const int slot = bq >> 1;
        kh = bq & 1;
        ld = 128;
        if (slot == 0) W = Wsame;
        else if (slot == 1) W = Wdiff;
        else if (slot < 2 + 2 * R) {
            int i = (slot - 2) >> 1;
            W = ((slot - 2) & 1) ? rW2 + (size_t)i * 16384
                                 : rW1 + (size_t)i * 16384;
        } else W = Wlast;
        img = g_wimg + (size_t)bq * FRAG_SZ;
    } else {
        W = Gw; ld = 64; kh = 0;
        img = g_wimg + (size_t)(2 * nsq) * FRAG_SZ;
    }
    uint4* out = (uint4*)img;
    for (int e = t; e < 2048; e += 256) {
        const int lane = e & 31, nj = (e >> 5) & 3, ks = (e >> 7) & 3, nw = e >> 9;
        const int n  = nw * 32 + nj * 8 + (lane >> 2);
        const int k0 = kh * 64 + ks * 16 + (lane & 3) * 2;
        const float* p = W + (size_t)n * ld + k0;
        uint32_t h0, l0, h1, l1;
        split_pack(p[0], p[1], h0, l0);
        split_pack(p[8], p[9], h1, l1);
        out[e] = make_uint4(h0, h1, l0, l1);
    }
}

// ---------------------------------------------------------------------------
// dst histogram / exclusive scan / permutation scatter
// ---------------------------------------------------------------------------
__device__ __forceinline__ int load_dst(const void* idx_raw, int E, int e,
                                        bool idx64) {
    return idx64 ? (int)((const long long*)idx_raw)[E + e]
                 : ((const int*)idx_raw)[E + e];
}

__global__ void hist_k(const void* __restrict__ idx_raw, int E) {
    const bool idx64 = (*(volatile unsigned*)&g_or) == 0u;
    for (int e = blockIdx.x * blockDim.x + threadIdx.x; e < E;
         e += gridDim.x * blockDim.x)
        atomicAdd(&g_cnt[load_dst(idx_raw, E, e, idx64)], 1);
}

__global__ void scan_k(int N) {
    __shared__ int wsum[32];
    const int t = threadIdx.x;
    const int lane = t & 31, wid = t >> 5;
    const int chunk = (N + 1023) / 1024;
    const int lo = t * chunk, hi = min(lo + chunk, N);
    int s = 0;
    for (int i = lo; i < hi; i++) s += g_cnt[i];
    int v = s;
#pragma unroll
    for (int o = 1; o < 32; o <<= 1) {
        int n = __shfl_up_sync(0xffffffffu, v, o);
        if (lane >= o) v += n;
    }
    if (lane == 31) wsum[wid] = v;
    __syncthreads();
    if (wid == 0) {
        int x = wsum[lane];
#pragma unroll
        for (int o = 1; o < 32; o <<= 1) {
            int n = __shfl_up_sync(0xffffffffu, x, o);
            if (lane >= o) x += n;
        }
        wsum[lane] = x;
    }
    __syncthreads();
    int run = (v - s) + (wid > 0 ? wsum[wid - 1] : 0);
    for (int i = lo; i < hi; i++) {
        int c = g_cnt[i];
        g_cnt[i] = run;
        run += c;
    }
}

__global__ void scatter_k(const void* __restrict__ idx_raw, int E) {
    const bool idx64 = (*(volatile unsigned*)&g_or) == 0u;
    for (int e = blockIdx.x * blockDim.x + threadIdx.x; e < E;
         e += gridDim.x * blockDim.x) {
        int d = load_dst(idx_raw, E, e, idx64);
        int pos = atomicAdd(&g_cnt[d], 1);
        g_perm[pos] = e;
    }
}

// ---------------------------------------------------------------------------
// tc_dual: M=64 tile; A = ssp(x) filled once; two sync-free GEMMs.
// ---------------------------------------------------------------------------
__global__ __launch_bounds__(256, 3)
void tc_dual(const float* __restrict__ x,
             const float* __restrict__ bsame, const float* __restrict__ bdiff,
             float* __restrict__ msged, float* __restrict__ tdiff, int N)
{
    extern __shared__ char smem[];
    const uint32_t sbase = smem_u32(smem);
    const int t     = threadIdx.x;
    const int row0  = blockIdx.x * 64;
    const int nrows = min(64, N - row0);
    TileIds id = make_ids(t);

    uint32_t aHi[2][2], aLo[2][2];
#pragma unroll
    for (int mi = 0; mi < 2; mi++) {
        aHi[0][mi] = sbase + 0 * TILE64 + id.aOff[mi];
        aLo[0][mi] = sbase + 1 * TILE64 + id.aOff[mi];
        aHi[1][mi] = sbase + 2 * TILE64 + id.aOff[mi];
        aLo[1][mi] = sbase + 3 * TILE64 + id.aOff[mi];
    }

    fill_64h<true>(smem, 0 * TILE64, 1 * TILE64, x, 128, row0, nrows, 0, t);
    fill_64h<true>(smem, 2 * TILE64, 3 * TILE64, x, 128, row0, nrows, 1, t);
    __syncthreads();

    float acc[2][4][4];
    const float* bp[2] = {bsame, bdiff};
    float*       op[2] = {msged, tdiff};

#pragma unroll
    for (int g = 0; g < 2; g++) {
        ZERO_ACC2(acc);
#pragma unroll
        for (int kh = 0; kh < 2; kh++) {
            const uint4* bimg = (const uint4*)(g_wimg + (size_t)(g * 2 + kh) * FRAG_SZ);
            mma_passG<2>(acc, aHi[kh], aLo[kh], bimg, id.nw, id.lane);
        }
#pragma unroll
        for (int mi = 0; mi < 2; mi++)
#pragma unroll
            for (int half = 0; half < 2; half++) {
                const int row = id.m_warp + 16 * mi + half * 8 + id.r_in;
                if (row >= nrows) continue;
                const size_t grow = (size_t)(row0 + row) * 128;
#pragma unroll
                for (int nj = 0; nj < 4; nj++) {
                    const int col = id.nw * 32 + 8 * nj + id.c_in;
                    float2 bb = *(const float2*)(bp[g] + col);
                    float2 o;
                    o.x = sspf(acc[mi][nj][half * 2 + 0] + bb.x);
                    o.y = sspf(acc[mi][nj][half * 2 + 1] + bb.y);
                    *(float2*)(op[g] + grow + col) = o;
                }
            }
    }
}

// ---------------------------------------------------------------------------
// res_chain: M=64 tile; R fused residual layers + final GEMM, one kernel.
// ---------------------------------------------------------------------------
__global__ __launch_bounds__(256, 3)
void res_chain(const float* __restrict__ msged, float* __restrict__ tbuf,
               const float* __restrict__ rb1, const float* __restrict__ rb2,
               const float* __restrict__ blast,
               const float* __restrict__ x, const float* __restrict__ u,
               float* __restrict__ out1, int N, int R)
{
    extern __shared__ char smem[];
    const uint32_t sbase = smem_u32(smem);
    const int t     = threadIdx.x;
    const int row0  = blockIdx.x * 64;
    const int nrows = min(64, N - row0);
    TileIds id = make_ids(t);

    uint32_t aHi[2][2], aLo[2][2];
#pragma unroll
    for (int mi = 0; mi < 2; mi++) {
        aHi[0][mi] = sbase + 0 * TILE64 + id.aOff[mi];
        aLo[0][mi] = sbase + 1 * TILE64 + id.aOff[mi];
        aHi[1][mi] = sbase + 2 * TILE64 + id.aOff[mi];
        aLo[1][mi] = sbase + 3 * TILE64 + id.aOff[mi];
    }
    const int hiB[2] = {0 * TILE64, 2 * TILE64};
    const int loB[2] = {1 * TILE64, 3 * TILE64};

    fill_64h<true>(smem, hiB[0], loB[0], msged, 128, row0, nrows, 0, t);
    fill_64h<true>(smem, hiB[1], loB[1], msged, 128, row0, nrows, 1, t);
    __syncthreads();

    const float* tin = msged;
    float acc[2][4][4];

    for (int i = 0; i < R; i++) {
        const float* b1 = rb1 + (size_t)i * 128;
        const float* b2 = rb2 + (size_t)i * 128;
        const char* img1 = g_wimg + (size_t)((2 + 2 * i) * 2) * FRAG_SZ;
        const char* img2 = g_wimg + (size_t)((3 + 2 * i) * 2) * FRAG_SZ;

        ZERO_ACC2(acc);
#pragma unroll
        for (int kh = 0; kh < 2; kh++)
            mma_passG<2>(acc, aHi[kh], aLo[kh],
                         (const uint4*)(img1 + (size_t)kh * FRAG_SZ),
                         id.nw, id.lane);
        __syncthreads();

#pragma unroll
        for (int mi = 0; mi < 2; mi++)
#pragma unroll
            for (int half = 0; half < 2; half++) {
                const int row = id.m_warp + 16 * mi + half * 8 + id.r_in;
#pragma unroll
                for (int nj = 0; nj < 4; nj++) {
                    const int col = id.nw * 32 + 8 * nj + id.c_in;
                    float2 bb = *(const float2*)(b1 + col);
                    float a = sspf(acc[mi][nj][half * 2 + 0] + bb.x);
                    float b = sspf(acc[mi][nj][half * 2 + 1] + bb.y);
                    uint32_t hi, lo;
                    split_pack(a, b, hi, lo);
                    const int kh = col >> 6;
                    uint32_t off = (uint32_t)row * RS + (col & 63) * 2;
                    *(uint32_t*)(smem + hiB[kh] + off) = hi;
                    *(uint32_t*)(smem + loB[kh] + off) = lo;
                }
            }
        __syncthreads();

        ZERO_ACC2(acc);
#pragma unroll
        for (int kh = 0; kh < 2; kh++)
            mma_passG<2>(acc, aHi[kh], aLo[kh],
                         (const uint4*)(img2 + (size_t)kh * FRAG_SZ),
                         id.nw, id.lane);
        __syncthreads();

        const bool wr = (i < R - 1);
#pragma unroll
        for (int mi = 0; mi < 2; mi++)
#pragma unroll
            for (int half = 0; half < 2; half++) {
                const int row = id.m_warp + 16 * mi + half * 8 + id.r_in;
                const bool ok = row < nrows;
                const size_t grow = (size_t)(row0 + row) * 128;
#pragma unroll
                for (int nj = 0; nj < 4; nj++) {
                    const int col = id.nw * 32 + 8 * nj + id.c_in;
                    float2 bb = *(const float2*)(b2 + col);
                    float2 tv = ok ? *(const float2*)(tin + grow + col)
                                   : make_float2(0.f, 0.f);
                    float ox = acc[mi][nj][half * 2 + 0] + bb.x + tv.x;
                    float oy = acc[mi][nj][half * 2 + 1] + bb.y + tv.y;
                    if (wr && ok) *(float2*)(tbuf + grow + col) = make_float2(ox, oy);
                    uint32_t hi, lo;
                    split_pack(sspf(ox), sspf(oy), hi, lo);
                    const int kh = col >> 6;
                    uint32_t off = (uint32_t)row * RS + (col & 63) * 2;
                    *(uint32_t*)(smem + hiB[kh] + off) = hi;
                    *(uint32_t*)(smem + loB[kh] + off) = lo;
                }
            }
        __syncthreads();
        tin = tbuf;
    }

    const char* imgL = g_wimg + (size_t)((2 + 2 * R) * 2) * FRAG_SZ;
    ZERO_ACC2(acc);
#pragma unroll
    for (int kh = 0; kh < 2; kh++)
        mma_passG<2>(acc, aHi[kh], aLo[kh],
                     (const uint4*)(imgL + (size_t)kh * FRAG_SZ),
                     id.nw, id.lane);
#pragma unroll
    for (int mi = 0; mi < 2; mi++)
#pragma unroll
        for (int half = 0; half < 2; half++) {
            const int row = id.m_warp + 16 * mi + half * 8 + id.r_in;
            if (row >= nrows) continue;
            const size_t grow = (size_t)(row0 + row) * 128;
#pragma unroll
            for (int nj = 0; nj < 4; nj++) {
                const int col = id.nw * 32 + 8 * nj + id.c_in;
                float2 bb = *(const float2*)(blast + col);
                float2 xv = *(const float2*)(x + grow + col);
                float2 uv = *(const float2*)(u + col);
                float2 o;
                o.x = acc[mi][nj][half * 2 + 0] + bb.x + xv.x * uv.x;
                o.y = acc[mi][nj][half * 2 + 1] + bb.y + xv.y * uv.y;
                *(float2*)(out1 + grow + col) = o;
            }
        }
}

// ---------------------------------------------------------------------------
// edge_kernel: 64 dst-sorted edges/block. Gate GEMM on permuted edge_attr;
// same-dst runs accumulated in registers, one red.v4 per run.
// ---------------------------------------------------------------------------
constexpr int GSTR = 136;
constexpr int ESM_TOT4 = 64 * GSTR * 4;    // 34816

__global__ __launch_bounds__(256, 3)
void edge_kernel(const void* __restrict__ idx_raw,
                 const float* __restrict__ ea,
                 const float* __restrict__ tdiff,
                 float* __restrict__ aggr,
                 const char* __restrict__ gwimg,
                 int E)
{
    extern __shared__ char smem[];
    const uint32_t sbase = smem_u32(smem);
    float* gsm = (float*)smem;

    const int t    = threadIdx.x;
    const int lane = t & 31;
    const int w    = t >> 5;
    const int e0   = blockIdx.x * 64;

    // prefetch (src,dst) via permutation; DRAM latency overlaps the ea fill
    const bool idx64 = (*(volatile unsigned*)&g_or) == 0u;
    const long long* ll = (const long long*)idx_raw;
    const int*       ii = (const int*)idx_raw;
    long long sReg = 0, dReg = 0;
    if (lane < 8) {
        int e = e0 + w * 8 + lane;
        if (e < E) {
            int pe = g_perm[e];
            if (idx64) { sReg = ll[pe]; dReg = ll[E + pe]; }
            else       { sReg = ii[pe]; dReg = ii[E + pe]; }
        }
    }

    const int m_warp = (w >> 2) * 32;
    const int nw     = w & 3;

    fill_ea_perm(smem, 0, 64 * RS, ea, g_perm, e0, E, t);
    __syncthreads();

    const int a_row = m_warp + ((lane >> 3) & 1) * 8 + (lane & 7);
    const int a_kh  = (lane >> 4) * 16;
    uint32_t aHiA[2], aLoA[2];
#pragma unroll
    for (int mi = 0; mi < 2; mi++) {
        uint32_t off = (uint32_t)(a_row + 16 * mi) * RS + a_kh;
        aHiA[mi] = sbase + off;
        aLoA[mi] = sbase + 64 * RS + off;
    }

    // batch A gathers (edges 0..3): latency hidden under the MMA
    float4 t4a[4];
#pragma unroll
    for (int el = 0; el < 4; el++) {
        long long s = __shfl_sync(0xffffffffu, sReg, el);
        t4a[el] = *(const float4*)(tdiff + (size_t)s * 128 + lane * 4);
    }

    float acc[2][4][4];
    ZERO_ACC2(acc);
    mma_passG<2>(acc, aHiA, aLoA, (const uint4*)gwimg, nw, lane);
    __syncthreads();   // ea consumed; reuse smem for fp32 gate

    const int r_in = lane >> 2;
    const int c_in = (lane & 3) * 2;
#pragma unroll
    for (int mi = 0; mi < 2; mi++)
#pragma unroll
        for (int half = 0; half < 2; half++) {
            const int row = m_warp + 16 * mi + half * 8 + r_in;
#pragma unroll
            for (int nj = 0; nj < 4; nj++) {
                const int col = nw * 32 + 8 * nj + c_in;
                float2 o;
                o.x = acc[mi][nj][half * 2 + 0];
                o.y = acc[mi][nj][half * 2 + 1];
                *(float2*)(gsm + (size_t)row * GSTR + col) = o;
            }
        }
    __syncthreads();

    // batch B gathers (edges 4..7)
    float4 t4b[4];
#pragma unroll
    for (int el = 0; el < 4; el++) {
        long long s = __shfl_sync(0xffffffffu, sReg, el + 4);
        t4b[el] = *(const float4*)(tdiff + (size_t)s * 128 + lane * 4);
    }

    // run-merged scatter: dsts sorted -> accumulate in regs, red per run
    long long dprev = -1;
    float4 macc = make_float4(0.f, 0.f, 0.f, 0.f);
#pragma unroll
    for (int el = 0; el < 8; el++) {
        int e = e0 + w * 8 + el;
        long long d = __shfl_sync(0xffffffffu, dReg, el);
        if (e < E) {
            float4 g4 = *(const float4*)(gsm + (size_t)(w * 8 + el) * GSTR + lane * 4);
            float4 tv = (el < 4) ? t4a[el] : t4b[el - 4];
            float4 m;
            m.x = g4.x * tv.x; m.y = g4.y * tv.y;
            m.z = g4.z * tv.z; m.w = g4.w * tv.w;
            if (d == dprev) {
                macc.x += m.x; macc.y += m.y; macc.z += m.z; macc.w += m.w;
            } else {
                if (dprev >= 0) {
                    float* p = aggr + (size_t)dprev * 128 + lane * 4;
                    asm volatile("red.global.add.v4.f32 [%0], {%1, %2, %3, %4};"
                                 :: "l"(p), "f"(macc.x), "f"(macc.y),
                                    "f"(macc.z), "f"(macc.w) : "memory");
                }
                macc = m;
                dprev = d;
            }
        }
    }
    if (dprev >= 0) {
        float* p = aggr + (size_t)dprev * 128 + lane * 4;
        asm volatile("red.global.add.v4.f32 [%0], {%1, %2, %3, %4};"
                     :: "l"(p), "f"(macc.x), "f"(macc.y),
                        "f"(macc.z), "f"(macc.w) : "memory");
    }
}

// ---------------------------------------------------------------------------
// launch
// ---------------------------------------------------------------------------
extern "C" void kernel_launch(void* const* d_in, const int* in_sizes, int n_in,
                              void* d_out, int out_size)
{
    const float* x     = (const float*)d_in[0];
    const void*  ei    = d_in[1];
    const float* ea    = (const float*)d_in[2];
    const float* Wsame = (const float*)d_in[3];
    const float* bsame = (const float*)d_in[4];
    const float* Wdiff = (const float*)d_in[5];
    const float* bdiff = (const float*)d_in[6];
    const float* Gw    = (const float*)d_in[7];
    const float* rW1   = (const float*)d_in[8];
    const float* rb1   = (const float*)d_in[9];
    const float* rW2   = (const float*)d_in[10];
    const float* rb2   = (const float*)d_in[11];
    const float* Wlast = (const float*)d_in[12];
    const float* blast = (const float*)d_in[13];
    const float* u     = (const float*)d_in[14];

    const int N = in_sizes[0] / 128;
    const int E = in_sizes[2] / 64;
    const int R = in_sizes[8] / (128 * 128);

    float* out1  = (float*)d_out;
    float* msged = (float*)d_out + (size_t)N * 128;

    float *tdiff_p, *t_p;
    char* wimg_p;
    cudaGetSymbolAddress((void**)&tdiff_p, g_tdiff);
    cudaGetSymbolAddress((void**)&t_p, g_t);
    cudaGetSymbolAddress((void**)&wimg_p, g_wimg);

    const int nblk = (N + 63) / 64;
    const int eblk = (E + 63) / 64;
    const int nsq  = 3 + 2 * R;

    cudaFuncSetAttribute(tc_dual,
                         cudaFuncAttributeMaxDynamicSharedMemorySize, SM_A64);
    cudaFuncSetAttribute(res_chain,
                         cudaFuncAttributeMaxDynamicSharedMemorySize, SM_A64);
    cudaFuncSetAttribute(edge_kernel,
                         cudaFuncAttributeMaxDynamicSharedMemorySize, ESM_TOT4);

    // weight frag images + idx dtype scan + histogram zero
    prep_w<<<2 * nsq + 1 + SCAN_BLKS + ZERO_BLKS, 256>>>(
        Wsame, Wdiff, rW1, rW2, Wlast, Gw, R, (const unsigned*)ei, E, N);

    // dst-sorted edge permutation
    hist_k<<<256, 256>>>(ei, E);
    scan_k<<<1, 1024>>>(N);
    scatter_k<<<256, 256>>>(ei, E);

    // t_same -> msged, t_diff -> g_tdiff (shared A fill)
    tc_dual<<<nblk, 256, SM_A64>>>(x, bsame, bdiff, msged, tdiff_p, N);

    // edge gate + message + run-merged scatter-add into msged
    edge_kernel<<<eblk, 256, ESM_TOT4>>>(ei, ea, tdiff_p, msged,
                                         wimg_p + (size_t)(2 * nsq) * FRAG_SZ, E);

    // residual stack + final GEMM, one kernel
    res_chain<<<nblk, 256, SM_A64>>>(msged, t_p, rb1, rb2,
                                     blast, x, u, out1, N, R);
}

// round 15
// speedup vs baseline: 1.2832x; 1.2832x over previous
#include <cuda_runtime.h>
#include <cuda_bf16.h>
#include <cstdint>

// ---------------------------------------------------------------------------
// InteractionModule (PhysNet message passing + residual stack)
// All GEMMs on HMMA mma.sync m16n8k16 bf16, hi/lo split 3-term emulation.
// Weights pre-converted once per replay into mma B-fragment images (prep_w,
// which also scans the edge-index dtype); GEMMs LDG B-frags from global
// (L2-hot): no W smem, no intra-GEMM syncs. Node kernels: M=64, 3 CTAs/SM.
// res_chain keeps the fp32 residual t in smem across all layers (no global
// round trips). Edge kernel: gathers split into 2 latency-hidden batches.
// 4 launches: prep_w(+scan), tc_dual, edge_kernel, res_chain.
// ---------------------------------------------------------------------------

#define SSP_LOG2 0.69314718055994530942f

__device__ __forceinline__ float sspf(float x) {
    return fmaxf(x, 0.0f) + __logf(1.0f + __expf(-fabsf(x))) - SSP_LOG2;
}

constexpr int FD   = 128;
constexpr int NMAX = 50176;

constexpr int RS      = 144;               // A-tile row stride bytes (9 x 16B)
constexpr int TILE64  = 64 * RS;           // 9216 B per [64 x 64] bf16 tile
constexpr int FRAG_SZ = 32768;             // one K-half B-frag image
constexpr int SM_A64  = 4 * TILE64;        // tc_dual smem: 36864 B
constexpr int TSTR    = 132;               // t smem row stride (floats)
constexpr int SM_RC   = 4 * TILE64 + 64 * TSTR * 4;   // res_chain: 70656 B

__device__ float    g_tdiff[NMAX * FD];
__device__ char     g_wimg[20 * FRAG_SZ];  // B-frag images (18 square + Gw)
__device__ unsigned g_or = 0u;             // idempotent across replays

// ---------------------------------------------------------------------------
// warp MMA helpers (generic PTX, sm_80+)
// ---------------------------------------------------------------------------
__device__ __forceinline__ uint32_t smem_u32(const void* p) {
    uint32_t a;
    asm("{ .reg .u64 t; cvta.to.shared.u64 t, %1; cvt.u32.u64 %0, t; }"
        : "=r"(a) : "l"(p));
    return a;
}
__device__ __forceinline__ void ldmx4(uint32_t* r, uint32_t addr) {
    asm volatile("ldmatrix.sync.aligned.m8n8.x4.shared.b16 {%0,%1,%2,%3}, [%4];"
                 : "=r"(r[0]), "=r"(r[1]), "=r"(r[2]), "=r"(r[3]) : "r"(addr));
}
__device__ __forceinline__ void mma16816(float* d, const uint32_t* a,
                                         uint32_t b0, uint32_t b1) {
    asm volatile("mma.sync.aligned.m16n8k16.row.col.f32.bf16.bf16.f32 "
                 "{%0,%1,%2,%3}, {%4,%5,%6,%7}, {%8,%9}, {%0,%1,%2,%3};"
                 : "+f"(d[0]), "+f"(d[1]), "+f"(d[2]), "+f"(d[3])
                 : "r"(a[0]), "r"(a[1]), "r"(a[2]), "r"(a[3]),
                   "r"(b0), "r"(b1));
}

__device__ __forceinline__ void split_pack(float a, float b,
                                           uint32_t& hi, uint32_t& lo) {
    __nv_bfloat16 ah = __float2bfloat16(a);
    __nv_bfloat16 bh = __float2bfloat16(b);
    __nv_bfloat16 al = __float2bfloat16(a - __bfloat162float(ah));
    __nv_bfloat16 bl = __float2bfloat16(b - __bfloat162float(bh));
    hi = ((uint32_t)*(uint16_t*)&bh << 16) | *(uint16_t*)&ah;
    lo = ((uint32_t)*(uint16_t*)&bl << 16) | *(uint16_t*)&al;
}

// fill a [64 x 64] fp32 sub-tile (col offset kh*64, row stride src_ld)
// into hi/lo bf16 A-tiles. Optionally stash raw fp32 values into tsm.
template <bool DO_SSP, bool STASH>
__device__ __forceinline__ void fill_64h(char* dst, int hi_off, int lo_off,
                                         const float* __restrict__ src,
                                         int src_ld, int row0, int nrows,
                                         int kh, int t, float* tsm) {
    const int kg = t & 7;
    const int r0 = t >> 3;
#pragma unroll
    for (int p = 0; p < 2; p++) {
        int row = r0 + p * 32;
        float v[8];
        if (row < nrows) {
            const float* rp = src + (size_t)(row0 + row) * src_ld + kh * 64 + kg * 8;
            float4 va = *(const float4*)(rp);
            float4 vb = *(const float4*)(rp + 4);
            v[0] = va.x; v[1] = va.y; v[2] = va.z; v[3] = va.w;
            v[4] = vb.x; v[5] = vb.y; v[6] = vb.z; v[7] = vb.w;
        } else {
#pragma unroll
            for (int i = 0; i < 8; i++) v[i] = 0.0f;
        }
        if (STASH) {
            float* tp = tsm + (size_t)row * TSTR + kh * 64 + kg * 8;
#pragma unroll
            for (int i = 0; i < 8; i++) tp[i] = v[i];
        }
        uint32_t hi[4], lo[4];
#pragma unroll
        for (int i = 0; i < 4; i++) {
            float a = v[2 * i], b = v[2 * i + 1];
            if (DO_SSP) { a = sspf(a); b = sspf(b); }
            split_pack(a, b, hi[i], lo[i]);
        }
        uint32_t off = (uint32_t)row * RS + kg * 16;
        *(uint4*)(dst + hi_off + off) = make_uint4(hi[0], hi[1], hi[2], hi[3]);
        *(uint4*)(dst + lo_off + off) = make_uint4(lo[0], lo[1], lo[2], lo[3]);
    }
}

// one K=64 MMA pass; A from smem (ldmatrix), B frags via LDG from frag image.
// image entry index: ((nw*4 + ks)*4 + nj)*32 + lane; uint4 = {h0,h1,l0,l1}.
template <int MI>
__device__ __forceinline__ void mma_passG(float acc[MI][4][4],
                                          const uint32_t aHiA[MI],
                                          const uint32_t aLoA[MI],
                                          const uint4* __restrict__ bimg,
                                          int nw, int lane) {
#pragma unroll
    for (int ks = 0; ks < 4; ks++) {
        uint4 b[4];
#pragma unroll
        for (int nj = 0; nj < 4; nj++)
            b[nj] = bimg[((nw * 4 + ks) * 4 + nj) * 32 + lane];
        const uint32_t koff = ks * 32;
        uint32_t af[MI][4];
#pragma unroll
        for (int mi = 0; mi < MI; mi++) ldmx4(af[mi], aHiA[mi] + koff);
#pragma unroll
        for (int mi = 0; mi < MI; mi++)
#pragma unroll
            for (int nj = 0; nj < 4; nj++) {
                mma16816(acc[mi][nj], af[mi], b[nj].x, b[nj].y);   // Ah*Wh
                mma16816(acc[mi][nj], af[mi], b[nj].z, b[nj].w);   // Ah*Wl
            }
#pragma unroll
        for (int mi = 0; mi < MI; mi++) ldmx4(af[mi], aLoA[mi] + koff);
#pragma unroll
        for (int mi = 0; mi < MI; mi++)
#pragma unroll
            for (int nj = 0; nj < 4; nj++)
                mma16816(acc[mi][nj], af[mi], b[nj].x, b[nj].y);   // Al*Wh
    }
}

#define ZERO_ACC2(acc) do {                                                   \
    _Pragma("unroll") for (int mi = 0; mi < 2; mi++)                          \
    _Pragma("unroll") for (int nj = 0; nj < 4; nj++)                          \
    _Pragma("unroll") for (int q = 0; q < 4; q++) (acc)[mi][nj][q] = 0.0f;    \
} while (0)

struct TileIds {
    int lane, w, m_warp, nw, r_in, c_in;
    uint32_t aOff[2];
};
__device__ __forceinline__ TileIds make_ids(int t) {
    TileIds id;
    id.lane  = t & 31;
    id.w     = t >> 5;
    id.m_warp = (id.w >> 2) * 32;
    id.nw    = id.w & 3;
    id.r_in  = id.lane >> 2;
    id.c_in  = (id.lane & 3) * 2;
    const int a_row = id.m_warp + ((id.lane >> 3) & 1) * 8 + (id.lane & 7);
    const int a_kh  = (id.lane >> 4) * 16;
#pragma unroll
    for (int mi = 0; mi < 2; mi++)
        id.aOff[mi] = (uint32_t)(a_row + 16 * mi) * RS + a_kh;
    return id;
}

// ---------------------------------------------------------------------------
// prep_w: weight B-frag images + edge-index dtype scan, one launch.
// ---------------------------------------------------------------------------
constexpr int SCAN_BLKS = 128;

__global__ void prep_w(const float* __restrict__ Wsame,
                       const float* __restrict__ Wdiff,
                       const float* __restrict__ rW1,
                       const float* __restrict__ rW2,
                       const float* __restrict__ Wlast,
                       const float* __restrict__ Gw, int R,
                       const unsigned* __restrict__ eiw, int E)
{
    const int bq = blockIdx.x, t = threadIdx.x;
    const int nsq = 3 + 2 * R;
    if (bq > 2 * nsq) {
        const int sb = bq - (2 * nsq + 1);
        unsigned v = 0;
        for (int i = sb * 256 + t; i < E; i += SCAN_BLKS * 256)
            v |= eiw[2 * i + 1];
        v = __reduce_or_sync(0xffffffffu, v);
        if ((t & 31) == 0 && v) atomicOr(&g_or, 1u);
        return;
    }
    const float* W;
    int ld, kh;
    char* img;
    if (bq < 2 * nsq) {
        const int slot = bq >> 1;
        kh = bq & 1;
        ld = 128;
        if (slot == 0) W = Wsame;
        else if (slot == 1) W = Wdiff;
        else if (slot < 2 + 2 * R) {
            int i = (slot - 2) >> 1;
            W = ((slot - 2) & 1) ? rW2 + (size_t)i * 16384
                                 : rW1 + (size_t)i * 16384;
        } else W = Wlast;
        img = g_wimg + (size_t)bq * FRAG_SZ;
    } else {
        W = Gw; ld = 64; kh = 0;
        img = g_wimg + (size_t)(2 * nsq) * FRAG_SZ;
    }
    uint4* out = (uint4*)img;
    for (int e = t; e < 2048; e += 256) {
        const int lane = e & 31, nj = (e >> 5) & 3, ks = (e >> 7) & 3, nw = e >> 9;
        const int n  = nw * 32 + nj * 8 + (lane >> 2);
        const int k0 = kh * 64 + ks * 16 + (lane & 3) * 2;
        const float* p = W + (size_t)n * ld + k0;
        uint32_t h0, l0, h1, l1;
        split_pack(p[0], p[1], h0, l0);
        split_pack(p[8], p[9], h1, l1);
        out[e] = make_uint4(h0, h1, l0, l1);
    }
}

// ---------------------------------------------------------------------------
// tc_dual: M=64 tile; A = ssp(x) filled once (kh0 hi/lo, kh1 hi/lo);
// two sync-free GEMMs (W_same -> msged, W_diff -> tdiff).
// ---------------------------------------------------------------------------
__global__ __launch_bounds__(256, 3)
void tc_dual(const float* __restrict__ x,
             const float* __restrict__ bsame, const float* __restrict__ bdiff,
             float* __restrict__ msged, float* __restrict__ tdiff, int N)
{
    extern __shared__ char smem[];
    const uint32_t sbase = smem_u32(smem);
    const int t     = threadIdx.x;
    const int row0  = blockIdx.x * 64;
    const int nrows = min(64, N - row0);
    TileIds id = make_ids(t);

    uint32_t aHi[2][2], aLo[2][2];
#pragma unroll
    for (int mi = 0; mi < 2; mi++) {
        aHi[0][mi] = sbase + 0 * TILE64 + id.aOff[mi];
        aLo[0][mi] = sbase + 1 * TILE64 + id.aOff[mi];
        aHi[1][mi] = sbase + 2 * TILE64 + id.aOff[mi];
        aLo[1][mi] = sbase + 3 * TILE64 + id.aOff[mi];
    }

    fill_64h<true, false>(smem, 0 * TILE64, 1 * TILE64, x, 128, row0, nrows, 0, t, nullptr);
    fill_64h<true, false>(smem, 2 * TILE64, 3 * TILE64, x, 128, row0, nrows, 1, t, nullptr);
    __syncthreads();

    float acc[2][4][4];
    const float* bp[2] = {bsame, bdiff};
    float*       op[2] = {msged, tdiff};

#pragma unroll
    for (int g = 0; g < 2; g++) {
        ZERO_ACC2(acc);
#pragma unroll
        for (int kh = 0; kh < 2; kh++) {
            const uint4* bimg = (const uint4*)(g_wimg + (size_t)(g * 2 + kh) * FRAG_SZ);
            mma_passG<2>(acc, aHi[kh], aLo[kh], bimg, id.nw, id.lane);
        }
#pragma unroll
        for (int mi = 0; mi < 2; mi++)
#pragma unroll
            for (int half = 0; half < 2; half++) {
                const int row = id.m_warp + 16 * mi + half * 8 + id.r_in;
                if (row >= nrows) continue;
                const size_t grow = (size_t)(row0 + row) * 128;
#pragma unroll
                for (int nj = 0; nj < 4; nj++) {
                    const int col = id.nw * 32 + 8 * nj + id.c_in;
                    float2 bb = *(const float2*)(bp[g] + col);
                    float2 o;
                    o.x = sspf(acc[mi][nj][half * 2 + 0] + bb.x);
                    o.y = sspf(acc[mi][nj][half * 2 + 1] + bb.y);
                    *(float2*)(op[g] + grow + col) = o;
                }
            }
    }
}

// ---------------------------------------------------------------------------
// res_chain: M=64 tile; R fused residual layers + final GEMM, one kernel.
// fp32 residual t lives in smem across all layers (no global round trips).
// smem: A tiles [0, 36864); t buffer [36864, 70656) stride TSTR floats.
// ---------------------------------------------------------------------------
__global__ __launch_bounds__(256, 3)
void res_chain(const float* __restrict__ msged,
               const float* __restrict__ rb1, const float* __restrict__ rb2,
               const float* __restrict__ blast,
               const float* __restrict__ x, const float* __restrict__ u,
               float* __restrict__ out1, int N, int R)
{
    extern __shared__ char smem[];
    const uint32_t sbase = smem_u32(smem);
    float* tsm = (float*)(smem + 4 * TILE64);
    const int t     = threadIdx.x;
    const int row0  = blockIdx.x * 64;
    const int nrows = min(64, N - row0);
    TileIds id = make_ids(t);

    uint32_t aHi[2][2], aLo[2][2];
#pragma unroll
    for (int mi = 0; mi < 2; mi++) {
        aHi[0][mi] = sbase + 0 * TILE64 + id.aOff[mi];
        aLo[0][mi] = sbase + 1 * TILE64 + id.aOff[mi];
        aHi[1][mi] = sbase + 2 * TILE64 + id.aOff[mi];
        aLo[1][mi] = sbase + 3 * TILE64 + id.aOff[mi];
    }
    const int hiB[2] = {0 * TILE64, 2 * TILE64};
    const int loB[2] = {1 * TILE64, 3 * TILE64};

    // initial fill: A = ssp(msged), stash raw msged fp32 into t smem
    fill_64h<true, true>(smem, hiB[0], loB[0], msged, 128, row0, nrows, 0, t, tsm);
    fill_64h<true, true>(smem, hiB[1], loB[1], msged, 128, row0, nrows, 1, t, tsm);
    __syncthreads();

    float acc[2][4][4];

    for (int i = 0; i < R; i++) {
        const float* b1 = rb1 + (size_t)i * 128;
        const float* b2 = rb2 + (size_t)i * 128;
        const char* img1 = g_wimg + (size_t)((2 + 2 * i) * 2) * FRAG_SZ;
        const char* img2 = g_wimg + (size_t)((3 + 2 * i) * 2) * FRAG_SZ;

        // phase 1: acc = ssp(t) @ W1^T (sync-free)
        ZERO_ACC2(acc);
#pragma unroll
        for (int kh = 0; kh < 2; kh++)
            mma_passG<2>(acc, aHi[kh], aLo[kh],
                         (const uint4*)(img1 + (size_t)kh * FRAG_SZ),
                         id.nw, id.lane);
        __syncthreads();   // all warps done reading A

        // convert y = ssp(acc + b1) -> A tiles
#pragma unroll
        for (int mi = 0; mi < 2; mi++)
#pragma unroll
            for (int half = 0; half < 2; half++) {
                const int row = id.m_warp + 16 * mi + half * 8 + id.r_in;
#pragma unroll
                for (int nj = 0; nj < 4; nj++) {
                    const int col = id.nw * 32 + 8 * nj + id.c_in;
                    float2 bb = *(const float2*)(b1 + col);
                    float a = sspf(acc[mi][nj][half * 2 + 0] + bb.x);
                    float b = sspf(acc[mi][nj][half * 2 + 1] + bb.y);
                    uint32_t hi, lo;
                    split_pack(a, b, hi, lo);
                    const int kh = col >> 6;
                    uint32_t off = (uint32_t)row * RS + (col & 63) * 2;
                    *(uint32_t*)(smem + hiB[kh] + off) = hi;
                    *(uint32_t*)(smem + loB[kh] + off) = lo;
                }
            }
        __syncthreads();

        // phase 2: acc = ssp(y) @ W2^T (sync-free)
        ZERO_ACC2(acc);
#pragma unroll
        for (int kh = 0; kh < 2; kh++)
            mma_passG<2>(acc, aHi[kh], aLo[kh],
                         (const uint4*)(img2 + (size_t)kh * FRAG_SZ),
                         id.nw, id.lane);
        __syncthreads();   // all warps done reading A

        // t' = t + acc + b2 : t read/write in smem; ssp(t') -> A tiles
#pragma unroll
        for (int mi = 0; mi < 2; mi++)
#pragma unroll
            for (int half = 0; half < 2; half++) {
                const int row = id.m_warp + 16 * mi + half * 8 + id.r_in;
#pragma unroll
                for (int nj = 0; nj < 4; nj++) {
                    const int col = id.nw * 32 + 8 * nj + id.c_in;
                    float2 bb = *(const float2*)(b2 + col);
                    float* tp = tsm + (size_t)row * TSTR + col;
                    float ox = acc[mi][nj][half * 2 + 0] + bb.x + tp[0];
                    float oy = acc[mi][nj][half * 2 + 1] + bb.y + tp[1];
                    tp[0] = ox; tp[1] = oy;
                    uint32_t hi, lo;
                    split_pack(sspf(ox), sspf(oy), hi, lo);
                    const int kh = col >> 6;
                    uint32_t off = (uint32_t)row * RS + (col & 63) * 2;
                    *(uint32_t*)(smem + hiB[kh] + off) = hi;
                    *(uint32_t*)(smem + loB[kh] + off) = lo;
                }
            }
        __syncthreads();
    }

    // final GEMM (slot 2+2R), sync-free
    const char* imgL = g_wimg + (size_t)((2 + 2 * R) * 2) * FRAG_SZ;
    ZERO_ACC2(acc);
#pragma unroll
    for (int kh = 0; kh < 2; kh++)
        mma_passG<2>(acc, aHi[kh], aLo[kh],
                     (const uint4*)(imgL + (size_t)kh * FRAG_SZ),
                     id.nw, id.lane);
#pragma unroll
    for (int mi = 0; mi < 2; mi++)
#pragma unroll
        for (int half = 0; half < 2; half++) {
            const int row = id.m_warp + 16 * mi + half * 8 + id.r_in;
            if (row >= nrows) continue;
            const size_t grow = (size_t)(row0 + row) * 128;
#pragma unroll
            for (int nj = 0; nj < 4; nj++) {
                const int col = id.nw * 32 + 8 * nj + id.c_in;
                float2 bb = *(const float2*)(blast + col);
                float2 xv = *(const float2*)(x + grow + col);
                float2 uv = *(const float2*)(u + col);
                float2 o;
                o.x = acc[mi][nj][half * 2 + 0] + bb.x + xv.x * uv.x;
                o.y = acc[mi][nj][half * 2 + 1] + bb.y + xv.y * uv.y;
                *(float2*)(out1 + grow + col) = o;
            }
        }
}

// ---------------------------------------------------------------------------
// edge_kernel: 64 edges/block, no W smem (B frags via LDG).
// smem: ea hi/lo [0, 18432); gate scratch overlaps [0, 34816).
// Gathers split in two 4-edge batches: batch A issued before the MMA
// (latency hidden under HMMA), batch B issued before batch-A reds.
// ---------------------------------------------------------------------------
constexpr int GSTR = 136;
constexpr int ESM_TOT4 = 64 * GSTR * 4;    // 34816

__global__ __launch_bounds__(256, 3)
void edge_kernel(const void* __restrict__ idx_raw,
                 const float* __restrict__ ea,
                 const float* __restrict__ tdiff,
                 float* __restrict__ aggr,
                 const char* __restrict__ gwimg,
                 int E)
{
    extern __shared__ char smem[];
    const uint32_t sbase = smem_u32(smem);
    float* gsm = (float*)smem;

    const int t    = threadIdx.x;
    const int lane = t & 31;
    const int w    = t >> 5;
    const int e0   = blockIdx.x * 64;
    const int nrows = min(64, E - e0);

    // prefetch (src,dst) first; DRAM latency overlaps the ea fill
    const bool idx64 = (*(volatile unsigned*)&g_or) == 0u;
    const long long* ll = (const long long*)idx_raw;
    const int*       ii = (const int*)idx_raw;
    long long sReg = 0, dReg = 0;
    if (lane < 8) {
        int e = e0 + w * 8 + lane;
        if (e < E) {
            if (idx64) { sReg = ll[e]; dReg = ll[E + e]; }
            else       { sReg = ii[e]; dReg = ii[E + e]; }
        }
    }

    // warp grid: 2 (m) x 4 (n); warp tile 32 x 32
    const int m_warp = (w >> 2) * 32;
    const int nw     = w & 3;

    fill_64h<false, false>(smem, 0, 64 * RS, ea, 64, e0, nrows, 0, t, nullptr);
    __syncthreads();

    const int a_row = m_warp + ((lane >> 3) & 1) * 8 + (lane & 7);
    const int a_kh  = (lane >> 4) * 16;
    uint32_t aHiA[2], aLoA[2];
#pragma unroll
    for (int mi = 0; mi < 2; mi++) {
        uint32_t off = (uint32_t)(a_row + 16 * mi) * RS + a_kh;
        aHiA[mi] = sbase + off;
        aLoA[mi] = sbase + 64 * RS + off;
    }

    // batch A gathers (edges 0..3): latency hidden under the MMA
    float4 t4a[4];
#pragma unroll
    for (int el = 0; el < 4; el++) {
        long long s = __shfl_sync(0xffffffffu, sReg, el);
        t4a[el] = *(const float4*)(tdiff + (size_t)s * 128 + lane * 4);
    }

    float acc[2][4][4];
    ZERO_ACC2(acc);
    mma_passG<2>(acc, aHiA, aLoA, (const uint4*)gwimg, nw, lane);
    __syncthreads();   // ea consumed; reuse smem for fp32 gate

    const int r_in = lane >> 2;
    const int c_in = (lane & 3) * 2;
#pragma unroll
    for (int mi = 0; mi < 2; mi++)
#pragma unroll
        for (int half = 0; half < 2; half++) {
            const int row = m_warp + 16 * mi + half * 8 + r_in;
#pragma unroll
            for (int nj = 0; nj < 4; nj++) {
                const int col = nw * 32 + 8 * nj + c_in;
                float2 o;
                o.x = acc[mi][nj][half * 2 + 0];
                o.y = acc[mi][nj][half * 2 + 1];
                *(float2*)(gsm + (size_t)row * GSTR + col) = o;
            }
        }
    __syncthreads();

    // batch B gathers (edges 4..7): latency hidden under batch-A reds
    float4 t4b[4];
#pragma unroll
    for (int el = 0; el < 4; el++) {
        long long s = __shfl_sync(0xffffffffu, sReg, el + 4);
        t4b[el] = *(const float4*)(tdiff + (size_t)s * 128 + lane * 4);
    }

#pragma unroll
    for (int el = 0; el < 4; el++) {
        int e = e0 + w * 8 + el;
        if (e >= E) break;
        long long d = __shfl_sync(0xffffffffu, dReg, el);
        float4 g4 = *(const float4*)(gsm + (size_t)(w * 8 + el) * GSTR + lane * 4);
        float4 m;
        m.x = g4.x * t4a[el].x; m.y = g4.y * t4a[el].y;
        m.z = g4.z * t4a[el].z; m.w = g4.w * t4a[el].w;
        float* p = aggr + (size_t)d * 128 + lane * 4;
        asm volatile("red.global.add.v4.f32 [%0], {%1, %2, %3, %4};"
                     :: "l"(p), "f"(m.x), "f"(m.y), "f"(m.z), "f"(m.w)
                     : "memory");
    }
#pragma unroll
    for (int el = 0; el < 4; el++) {
        int e = e0 + w * 8 + 4 + el;
        if (e >= E) break;
        long long d = __shfl_sync(0xffffffffu, dReg, el + 4);
        float4 g4 = *(const float4*)(gsm + (size_t)(w * 8 + 4 + el) * GSTR + lane * 4);
        float4 m;
        m.x = g4.x * t4b[el].x; m.y = g4.y * t4b[el].y;
        m.z = g4.z * t4b[el].z; m.w = g4.w * t4b[el].w;
        float* p = aggr + (size_t)d * 128 + lane * 4;
        asm volatile("red.global.add.v4.f32 [%0], {%1, %2, %3, %4};"
                     :: "l"(p), "f"(m.x), "f"(m.y), "f"(m.z), "f"(m.w)
                     : "memory");
    }
}

// ---------------------------------------------------------------------------
// launch
// ---------------------------------------------------------------------------
extern "C" void kernel_launch(void* const* d_in, const int* in_sizes, int n_in,
                              void* d_out, int out_size)
{
    const float* x     = (const float*)d_in[0];
    const void*  ei    = d_in[1];
    const float* ea    = (const float*)d_in[2];
    const float* Wsame = (const float*)d_in[3];
    const float* bsame = (const float*)d_in[4];
    const float* Wdiff = (const float*)d_in[5];
    const float* bdiff = (const float*)d_in[6];
    const float* Gw    = (const float*)d_in[7];
    const float* rW1   = (const float*)d_in[8];
    const float* rb1   = (const float*)d_in[9];
    const float* rW2   = (const float*)d_in[10];
    const float* rb2   = (const float*)d_in[11];
    const float* Wlast = (const float*)d_in[12];
    const float* blast = (const float*)d_in[13];
    const float* u     = (const float*)d_in[14];

    const int N = in_sizes[0] / 128;
    const int E = in_sizes[2] / 64;
    const int R = in_sizes[8] / (128 * 128);

    float* out1  = (float*)d_out;
    float* msged = (float*)d_out + (size_t)N * 128;

    float* tdiff_p;
    char* wimg_p;
    cudaGetSymbolAddress((void**)&tdiff_p, g_tdiff);
    cudaGetSymbolAddress((void**)&wimg_p, g_wimg);

    const int nblk = (N + 63) / 64;
    const int eblk = (E + 63) / 64;
    const int nsq  = 3 + 2 * R;

    cudaFuncSetAttribute(tc_dual,
                         cudaFuncAttributeMaxDynamicSharedMemorySize, SM_A64);
    cudaFuncSetAttribute(res_chain,
                         cudaFuncAttributeMaxDynamicSharedMemorySize, SM_RC);
    cudaFuncSetAttribute(edge_kernel,
                         cudaFuncAttributeMaxDynamicSharedMemorySize, ESM_TOT4);

    // weight frag-image prep + idx dtype scan (deterministic per replay)
    prep_w<<<2 * nsq + 1 + SCAN_BLKS, 256>>>(Wsame, Wdiff, rW1, rW2, Wlast,
                                             Gw, R, (const unsigned*)ei, E);

    // t_same -> msged, t_diff -> g_tdiff (shared A fill)
    tc_dual<<<nblk, 256, SM_A64>>>(x, bsame, bdiff, msged, tdiff_p, N);

    // edge gate + message + scatter-add into msged
    edge_kernel<<<eblk, 256, ESM_TOT4>>>(ei, ea, tdiff_p, msged,
                                         wimg_p + (size_t)(2 * nsq) * FRAG_SZ, E);

    // residual stack + final GEMM, one kernel (t resident in smem)
    res_chain<<<nblk, 256, SM_RC>>>(msged, rb1, rb2,
                                    blast, x, u, out1, N, R);
}